// round 9
// baseline (speedup 1.0000x reference)
#include <cuda_runtime.h>
#include <cstdint>

// FP8 E4M3 bit-plane multiply -> exact FP32 bit-plane.
// v3: R5 structure (1 elem/thread, shuffle-coalesced float4 stores) made
// persistent: grid = SMs * 8 CTAs, grid-stride loop -> single wave, no
// wave-transition overhead, continuous HBM streaming per SM.

__device__ __forceinline__ uint32_t pack_byte(uint4 lo, uint4 hi) {
    // lo = {s, e3, e2, e1}, hi = {e0, m2, m1, m0}; result bit7=s .. bit0=m0.
    // bit-plane float is 0x3F800000 (1.0f) or 0x0 -> bit 23 carries the value.
    uint32_t v;
    v  = (lo.x >> 16) & 0x80u;  // s  -> bit 7
    v |= (lo.y >> 17) & 0x40u;  // e3 -> bit 6
    v |= (lo.z >> 18) & 0x20u;  // e2 -> bit 5
    v |= (lo.w >> 19) & 0x10u;  // e1 -> bit 4
    v |= (hi.x >> 20) & 0x08u;  // e0 -> bit 3
    v |= (hi.y >> 21) & 0x04u;  // m2 -> bit 2
    v |= (hi.z >> 22) & 0x02u;  // m1 -> bit 1
    v |= (hi.w >> 23) & 0x01u;  // m0 -> bit 0
    return v;
}

// Exact FP8(E4M3) x FP8 -> FP32 bit pattern from two packed FP8 bytes.
__device__ __forceinline__ uint32_t fp8_mul_word(uint32_t va, uint32_t vb) {
    // decode A
    uint32_t ma = va & 7u, ea4 = (va >> 3) & 15u;
    int pa = 31 - __clz(ma | 1u);                 // m=0 -> 0 (frac stays 0)
    uint32_t fa = ea4 ? (ma + 8u) : (ma << (3 - pa));
    int      ea = ea4 ? (int)ea4 + 120 : 118 + pa;
    // decode B
    uint32_t mb = vb & 7u, eb4 = (vb >> 3) & 15u;
    int pb = 31 - __clz(mb | 1u);
    uint32_t fb = eb4 ? (mb + 8u) : (mb << (3 - pb));
    int      eb = eb4 ? (int)eb4 + 120 : 118 + pb;

    const uint32_t p     = fa * fb;               // [64,225] when both nonzero
    const uint32_t carry = p >> 7;                // leading one at bit 7 vs 6
    const uint32_t pn    = p << (1u - carry);     // normalize leading one -> bit 7
    const int      eo    = ea + eb - 127 + (int)carry;

    uint32_t body = ((uint32_t)eo << 23) | ((pn & 0x7Fu) << 16);
    const bool nz = ((va & 0x7Fu) != 0u) & ((vb & 0x7Fu) != 0u);
    return (((va ^ vb) & 0x80u) << 24) | (nz ? body : 0u);
}

__global__ void __launch_bounds__(256, 8)
spike_fp8_mul_kernel(const uint4* __restrict__ A4,
                     const uint4* __restrict__ B4,
                     float4* __restrict__ O4,
                     int n_elem) {
    const int lane   = threadIdx.x & 31;
    const int wslot  = (int)threadIdx.x - lane;      // warp slot within block
    const int stride = gridDim.x * blockDim.x;       // elements per grid pass
    const uint32_t j0 = (uint32_t)(lane & 7) * 4u;
    const int      sl = lane >> 3;

    for (int base = blockIdx.x * blockDim.x; base < n_elem; base += stride) {
        const int elem = base + threadIdx.x;
        const int eb   = base + wslot;               // warp's base element

        uint32_t word = 0u;
        if (elem < n_elem) {
            const uint4 al = A4[(size_t)elem * 2 + 0];
            const uint4 ah = A4[(size_t)elem * 2 + 1];
            const uint4 bl = B4[(size_t)elem * 2 + 0];
            const uint4 bh = B4[(size_t)elem * 2 + 1];
            word = fp8_mul_word(pack_byte(al, ah), pack_byte(bl, bh));
        }

        // Warp-coalesced output: iteration k writes float4 index eb*8 + k*32 + lane
        // (512B contiguous per warp per iteration; 4KB contiguous per warp total).
        // That float4 belongs to element eb + k*4 + (lane>>3),
        // bit group [4*(lane&7), +4).
#pragma unroll
        for (int k = 0; k < 8; ++k) {
            const uint32_t w  = __shfl_sync(0xFFFFFFFFu, word, k * 4 + sl);
            const uint32_t ws = w << j0;   // target bit group now at bits 31..28
            float4 f;
            f.x = __uint_as_float(((int)(ws      ) >> 31) & 0x3F800000);
            f.y = __uint_as_float(((int)(ws << 1) >> 31) & 0x3F800000);
            f.z = __uint_as_float(((int)(ws << 2) >> 31) & 0x3F800000);
            f.w = __uint_as_float(((int)(ws << 3) >> 31) & 0x3F800000);
            const int src_elem = eb + k * 4 + sl;
            if (src_elem < n_elem)
                O4[(size_t)eb * 8 + (size_t)k * 32 + lane] = f;
        }
    }
}

extern "C" void kernel_launch(void* const* d_in, const int* in_sizes, int n_in,
                              void* d_out, int out_size) {
    const uint4* A4 = (const uint4*)d_in[0];
    const uint4* B4 = (const uint4*)d_in[1];
    float4* O4 = (float4*)d_out;

    const int n_elem  = in_sizes[0] / 8;   // 1024*4096 = 4,194,304
    const int threads = 256;

    // Persistent single-wave grid: 8 CTAs per SM (warp-limited at 256 thr).
    int sms = 148;
    cudaDeviceGetAttribute(&sms, cudaDevAttrMultiProcessorCount, 0);
    int blocks = sms * 8;
    const int max_blocks = (n_elem + threads - 1) / threads;
    if (blocks > max_blocks) blocks = max_blocks;

    spike_fp8_mul_kernel<<<blocks, threads>>>(A4, B4, O4, n_elem);
}

// round 10
// speedup vs baseline: 1.1330x; 1.1330x over previous
#include <cuda_runtime.h>
#include <cstdint>

// FP8 E4M3 bit-plane multiply -> exact FP32 bit-plane.
// v4 = R5 structure (best so far: 1 elem/thread, one-shot grid, shuffle-
// coalesced float4 stores) + __ldcs streaming loads so the read-once input
// stream doesn't pollute L2 against the write stream.

__device__ __forceinline__ uint32_t pack_byte(uint4 lo, uint4 hi) {
    // lo = {s, e3, e2, e1}, hi = {e0, m2, m1, m0}; result bit7=s .. bit0=m0.
    // bit-plane float is 0x3F800000 (1.0f) or 0x0 -> bit 23 carries the value.
    uint32_t v;
    v  = (lo.x >> 16) & 0x80u;  // s  -> bit 7
    v |= (lo.y >> 17) & 0x40u;  // e3 -> bit 6
    v |= (lo.z >> 18) & 0x20u;  // e2 -> bit 5
    v |= (lo.w >> 19) & 0x10u;  // e1 -> bit 4
    v |= (hi.x >> 20) & 0x08u;  // e0 -> bit 3
    v |= (hi.y >> 21) & 0x04u;  // m2 -> bit 2
    v |= (hi.z >> 22) & 0x02u;  // m1 -> bit 1
    v |= (hi.w >> 23) & 0x01u;  // m0 -> bit 0
    return v;
}

// Exact FP8(E4M3) x FP8 -> FP32 bit pattern from two packed FP8 bytes.
__device__ __forceinline__ uint32_t fp8_mul_word(uint32_t va, uint32_t vb) {
    // decode A
    uint32_t ma = va & 7u, ea4 = (va >> 3) & 15u;
    int pa = 31 - __clz(ma | 1u);                 // m=0 -> 0 (frac stays 0)
    uint32_t fa = ea4 ? (ma + 8u) : (ma << (3 - pa));
    int      ea = ea4 ? (int)ea4 + 120 : 118 + pa;
    // decode B
    uint32_t mb = vb & 7u, eb4 = (vb >> 3) & 15u;
    int pb = 31 - __clz(mb | 1u);
    uint32_t fb = eb4 ? (mb + 8u) : (mb << (3 - pb));
    int      eb = eb4 ? (int)eb4 + 120 : 118 + pb;

    const uint32_t p     = fa * fb;               // [64,225] when both nonzero
    const uint32_t carry = p >> 7;                // leading one at bit 7 vs 6
    const uint32_t pn    = p << (1u - carry);     // normalize leading one -> bit 7
    const int      eo    = ea + eb - 127 + (int)carry;

    uint32_t body = ((uint32_t)eo << 23) | ((pn & 0x7Fu) << 16);
    const bool nz = ((va & 0x7Fu) != 0u) & ((vb & 0x7Fu) != 0u);
    return (((va ^ vb) & 0x80u) << 24) | (nz ? body : 0u);
}

__global__ void __launch_bounds__(256, 8)
spike_fp8_mul_kernel(const uint4* __restrict__ A4,
                     const uint4* __restrict__ B4,
                     float4* __restrict__ O4,
                     int n_elem) {
    const int tid  = blockIdx.x * blockDim.x + threadIdx.x;
    const int lane = threadIdx.x & 31;
    const int eb   = tid - lane;          // warp's base element
    const int elem = tid;

    uint32_t word = 0u;
    if (elem < n_elem) {
        // Streaming loads: inputs are read exactly once -> evict-first in L2.
        const uint4 al = __ldcs(&A4[(size_t)elem * 2 + 0]);
        const uint4 ah = __ldcs(&A4[(size_t)elem * 2 + 1]);
        const uint4 bl = __ldcs(&B4[(size_t)elem * 2 + 0]);
        const uint4 bh = __ldcs(&B4[(size_t)elem * 2 + 1]);
        word = fp8_mul_word(pack_byte(al, ah), pack_byte(bl, bh));
    }

    // Warp-coalesced output: iteration k writes float4 index eb*8 + k*32 + lane
    // (512B contiguous per warp per iteration; 4KB contiguous per warp total).
    // That float4 belongs to element eb + k*4 + (lane>>3),
    // bit group [4*(lane&7), +4).
    const uint32_t j0 = (uint32_t)(lane & 7) * 4u;
    const int      sl = lane >> 3;
#pragma unroll
    for (int k = 0; k < 8; ++k) {
        const uint32_t w  = __shfl_sync(0xFFFFFFFFu, word, k * 4 + sl);
        const uint32_t ws = w << j0;     // target bit group now at bits 31..28
        float4 f;
        f.x = __uint_as_float(((int)(ws      ) >> 31) & 0x3F800000);
        f.y = __uint_as_float(((int)(ws << 1) >> 31) & 0x3F800000);
        f.z = __uint_as_float(((int)(ws << 2) >> 31) & 0x3F800000);
        f.w = __uint_as_float(((int)(ws << 3) >> 31) & 0x3F800000);
        const int src_elem = eb + k * 4 + sl;
        if (src_elem < n_elem)
            O4[(size_t)eb * 8 + (size_t)k * 32 + lane] = f;
    }
}

extern "C" void kernel_launch(void* const* d_in, const int* in_sizes, int n_in,
                              void* d_out, int out_size) {
    const uint4* A4 = (const uint4*)d_in[0];
    const uint4* B4 = (const uint4*)d_in[1];
    float4* O4 = (float4*)d_out;

    const int n_elem  = in_sizes[0] / 8;   // 1024*4096 = 4,194,304
    const int threads = 256;
    const int blocks  = (n_elem + threads - 1) / threads;

    spike_fp8_mul_kernel<<<blocks, threads>>>(A4, B4, O4, n_elem);
}

// round 13
// speedup vs baseline: 1.1482x; 1.0135x over previous
#include <cuda_runtime.h>
#include <cstdint>

// FP8 E4M3 bit-plane multiply -> exact FP32 bit-plane.
// v5 = R5 structure (1 elem/thread, one-shot grid, shuffle-coalesced float4
// stores) with 128-thread CTAs: 16 CTAs/SM instead of 8 at the same thread
// count -> finer CTA retire/refill granularity -> higher avg warps_active.

__device__ __forceinline__ uint32_t pack_byte(uint4 lo, uint4 hi) {
    // lo = {s, e3, e2, e1}, hi = {e0, m2, m1, m0}; result bit7=s .. bit0=m0.
    // bit-plane float is 0x3F800000 (1.0f) or 0x0 -> bit 23 carries the value.
    uint32_t v;
    v  = (lo.x >> 16) & 0x80u;  // s  -> bit 7
    v |= (lo.y >> 17) & 0x40u;  // e3 -> bit 6
    v |= (lo.z >> 18) & 0x20u;  // e2 -> bit 5
    v |= (lo.w >> 19) & 0x10u;  // e1 -> bit 4
    v |= (hi.x >> 20) & 0x08u;  // e0 -> bit 3
    v |= (hi.y >> 21) & 0x04u;  // m2 -> bit 2
    v |= (hi.z >> 22) & 0x02u;  // m1 -> bit 1
    v |= (hi.w >> 23) & 0x01u;  // m0 -> bit 0
    return v;
}

// Exact FP8(E4M3) x FP8 -> FP32 bit pattern from two packed FP8 bytes.
__device__ __forceinline__ uint32_t fp8_mul_word(uint32_t va, uint32_t vb) {
    // decode A
    uint32_t ma = va & 7u, ea4 = (va >> 3) & 15u;
    int pa = 31 - __clz(ma | 1u);                 // m=0 -> 0 (frac stays 0)
    uint32_t fa = ea4 ? (ma + 8u) : (ma << (3 - pa));
    int      ea = ea4 ? (int)ea4 + 120 : 118 + pa;
    // decode B
    uint32_t mb = vb & 7u, eb4 = (vb >> 3) & 15u;
    int pb = 31 - __clz(mb | 1u);
    uint32_t fb = eb4 ? (mb + 8u) : (mb << (3 - pb));
    int      eb = eb4 ? (int)eb4 + 120 : 118 + pb;

    const uint32_t p     = fa * fb;               // [64,225] when both nonzero
    const uint32_t carry = p >> 7;                // leading one at bit 7 vs 6
    const uint32_t pn    = p << (1u - carry);     // normalize leading one -> bit 7
    const int      eo    = ea + eb - 127 + (int)carry;

    uint32_t body = ((uint32_t)eo << 23) | ((pn & 0x7Fu) << 16);
    const bool nz = ((va & 0x7Fu) != 0u) & ((vb & 0x7Fu) != 0u);
    return (((va ^ vb) & 0x80u) << 24) | (nz ? body : 0u);
}

__global__ void __launch_bounds__(128, 16)
spike_fp8_mul_kernel(const uint4* __restrict__ A4,
                     const uint4* __restrict__ B4,
                     float4* __restrict__ O4,
                     int n_elem) {
    const int tid  = blockIdx.x * blockDim.x + threadIdx.x;
    const int lane = threadIdx.x & 31;
    const int eb   = tid - lane;          // warp's base element
    const int elem = tid;

    uint32_t word = 0u;
    if (elem < n_elem) {
        const uint4 al = A4[(size_t)elem * 2 + 0];
        const uint4 ah = A4[(size_t)elem * 2 + 1];
        const uint4 bl = B4[(size_t)elem * 2 + 0];
        const uint4 bh = B4[(size_t)elem * 2 + 1];
        word = fp8_mul_word(pack_byte(al, ah), pack_byte(bl, bh));
    }

    // Warp-coalesced output: iteration k writes float4 index eb*8 + k*32 + lane
    // (512B contiguous per warp per iteration; 4KB contiguous per warp total).
    // That float4 belongs to element eb + k*4 + (lane>>3),
    // bit group [4*(lane&7), +4).
    const uint32_t j0 = (uint32_t)(lane & 7) * 4u;
    const int      sl = lane >> 3;
#pragma unroll
    for (int k = 0; k < 8; ++k) {
        const uint32_t w  = __shfl_sync(0xFFFFFFFFu, word, k * 4 + sl);
        const uint32_t ws = w << j0;     // target bit group now at bits 31..28
        float4 f;
        f.x = __uint_as_float(((int)(ws      ) >> 31) & 0x3F800000);
        f.y = __uint_as_float(((int)(ws << 1) >> 31) & 0x3F800000);
        f.z = __uint_as_float(((int)(ws << 2) >> 31) & 0x3F800000);
        f.w = __uint_as_float(((int)(ws << 3) >> 31) & 0x3F800000);
        const int src_elem = eb + k * 4 + sl;
        if (src_elem < n_elem)
            O4[(size_t)eb * 8 + (size_t)k * 32 + lane] = f;
    }
}

extern "C" void kernel_launch(void* const* d_in, const int* in_sizes, int n_in,
                              void* d_out, int out_size) {
    const uint4* A4 = (const uint4*)d_in[0];
    const uint4* B4 = (const uint4*)d_in[1];
    float4* O4 = (float4*)d_out;

    const int n_elem  = in_sizes[0] / 8;   // 1024*4096 = 4,194,304
    const int threads = 128;
    const int blocks  = (n_elem + threads - 1) / threads;

    spike_fp8_mul_kernel<<<blocks, threads>>>(A4, B4, O4, n_elem);
}